// round 14
// baseline (speedup 1.0000x reference)
#include <cuda_runtime.h>
#include <cstdint>

#define S 2048
#define B 32
#define I 256
#define H 256
#define G4 1024
#define NCTA 128
#define NTHR2 512
#define GD 16     // CTAs per group
#define SENT 0x7FC000AAu   // NaN sentinel (gates can never produce NaN)

// Static device scratch (no cudaMalloc allowed).
__device__ float g_Wp[I * G4];                 // packed input weights  [k][colp]
__device__ float g_Up[H * G4];                 // packed recurrent wts  [k][colp]
__device__ float g_bp[G4];                     // packed bias
__device__ float g_xg[(size_t)S * B * G4];     // input projections [t][cta][bq][64]
__device__ float g_hseq[(size_t)(S + 1) * B * H];  // h history [t][g][dim][bq]; slot 0 = zeros

// colp mapping: gate = colp&3 (0=f,1=i,2=c,3=o), jl = (colp>>2)&15, l = colp>>6
// hidden dim j = l*16 + jl. CTA (g,l) owns batches 4g..4g+3 and cols l*64..l*64+63.
__global__ void pack_kernel(
    const float* __restrict__ Wf, const float* __restrict__ Wi,
    const float* __restrict__ Wc, const float* __restrict__ Wo,
    const float* __restrict__ Uf, const float* __restrict__ Ui,
    const float* __restrict__ Uc, const float* __restrict__ Uo,
    const float* __restrict__ bf, const float* __restrict__ bi,
    const float* __restrict__ bc, const float* __restrict__ bo)
{
    int idx = blockIdx.x * blockDim.x + threadIdx.x;
    if (idx < I * G4) {
        int k    = idx >> 10;
        int colp = idx & 1023;
        int g    = colp & 3;
        int jl   = (colp >> 2) & 15;
        int l    = colp >> 6;
        int j    = l * 16 + jl;
        const float* W = (g == 0) ? Wf : (g == 1) ? Wi : (g == 2) ? Wc : Wo;
        const float* U = (g == 0) ? Uf : (g == 1) ? Ui : (g == 2) ? Uc : Uo;
        g_Wp[idx] = W[k * H + j];
        g_Up[idx] = U[k * H + j];
        if (k == 0) {
            const float* bv = (g == 0) ? bf : (g == 1) ? bi : (g == 2) ? bc : bo;
            g_bp[colp] = bv[j];
        }
    }
}

// Prefill h history: slot 0 = zeros (h_{-1}), slots 1..S = sentinel NaN.
__global__ void hinit_kernel()
{
    size_t tot = (size_t)(S + 1) * B * H;
    size_t stride = (size_t)gridDim.x * blockDim.x;
    float sent = __uint_as_float(SENT);
    for (size_t i = (size_t)blockIdx.x * blockDim.x + threadIdx.x; i < tot; i += stride)
        g_hseq[i] = (i < (size_t)B * H) ? 0.f : sent;
}

// ---------------- Phase 1: xg = x @ Wp + bp, output [t][cta][bq][64] ----------------
#define BM 128
#define BN 64
#define BK 16

__global__ __launch_bounds__(256) void gemm_xg_kernel(const float* __restrict__ x)
{
    __shared__ float As[BK][BM + 4];   // transposed A tile
    __shared__ float Bs[BK][BN];

    int tid = threadIdx.x;
    int r0 = blockIdx.y * BM;   // rows r = t*B + b
    int c0 = blockIdx.x * BN;
    int tr = tid >> 4;          // 0..15 -> rows tr*8..+7
    int tc = tid & 15;          // 0..15 -> cols tc*4..+3

    int aRow = tid >> 1;              // 0..127
    int aK   = (tid & 1) * 8;         // 0 or 8
    int bK   = tid >> 4;              // 0..15
    int bC   = (tid & 15) << 2;       // 0..60

    int r  = r0 + aRow;
    int bb = r & 31;
    int tt = r >> 5;
    const float* aptr = x + ((size_t)bb * S + tt) * I + aK;

    float acc[8][4];
#pragma unroll
    for (int i2 = 0; i2 < 8; ++i2)
#pragma unroll
        for (int j2 = 0; j2 < 4; ++j2) acc[i2][j2] = 0.f;

    for (int k0 = 0; k0 < I; k0 += BK) {
        float4 a1 = *(const float4*)(aptr + k0);
        float4 a2 = *(const float4*)(aptr + k0 + 4);
        As[aK + 0][aRow] = a1.x;
        As[aK + 1][aRow] = a1.y;
        As[aK + 2][aRow] = a1.z;
        As[aK + 3][aRow] = a1.w;
        As[aK + 4][aRow] = a2.x;
        As[aK + 5][aRow] = a2.y;
        As[aK + 6][aRow] = a2.z;
        As[aK + 7][aRow] = a2.w;
        float4 bv = *(const float4*)(g_Wp + (size_t)(k0 + bK) * G4 + c0 + bC);
        *(float4*)&Bs[bK][bC] = bv;
        __syncthreads();
#pragma unroll
        for (int kk = 0; kk < BK; ++kk) {
            float4 b4 = *(const float4*)&Bs[kk][tc << 2];
            float4 a4lo = *(const float4*)&As[kk][tr << 3];
            float4 a4hi = *(const float4*)&As[kk][(tr << 3) + 4];
            float av[8] = {a4lo.x, a4lo.y, a4lo.z, a4lo.w, a4hi.x, a4hi.y, a4hi.z, a4hi.w};
#pragma unroll
            for (int i2 = 0; i2 < 8; ++i2) {
                acc[i2][0] = fmaf(av[i2], b4.x, acc[i2][0]);
                acc[i2][1] = fmaf(av[i2], b4.y, acc[i2][1]);
                acc[i2][2] = fmaf(av[i2], b4.z, acc[i2][2]);
                acc[i2][3] = fmaf(av[i2], b4.w, acc[i2][3]);
            }
        }
        __syncthreads();
    }

    int col = c0 + (tc << 2);         // global packed col, 4-aligned
    int l   = col >> 6;
    int c63 = col & 63;               // stays within 64-block for the float4
    float4 bias = *(const float4*)&g_bp[col];
#pragma unroll
    for (int i2 = 0; i2 < 8; ++i2) {
        int rr  = r0 + (tr << 3) + i2;
        int tt2 = rr >> 5;
        int bb2 = rr & 31;
        int grp = bb2 >> 2;
        int bq  = bb2 & 3;
        float4 o;
        o.x = acc[i2][0] + bias.x;
        o.y = acc[i2][1] + bias.y;
        o.z = acc[i2][2] + bias.z;
        o.w = acc[i2][3] + bias.w;
        *(float4*)(g_xg + (((size_t)tt2 * NCTA + grp * GD + l) * 4 + bq) * 64 + c63) = o;
    }
}

// ---------------- Phase 2: warp-autonomous persistent recurrence ----------------
__device__ __forceinline__ float sig_(float v) {
    return __fdividef(1.f, 1.f + __expf(-v));
}
__device__ __forceinline__ float tanh_(float v) {
    return 1.f - __fdividef(2.f, 1.f + __expf(2.f * v));
}

__global__ __launch_bounds__(NTHR2, 1) void lstm_kernel(float* __restrict__ out, int out_size)
{
    int cta  = blockIdx.x;
    int g    = cta >> 4;              // batch group
    int l    = cta & 15;              // dim slice
    int tid  = threadIdx.x;
    int lane = tid & 31;
    int w    = tid >> 5;              // warp -> hidden dim l*16+w (all 4 gates)

    // hoist U: u2[iq][p] = (U[k][col], U[k][col+1]) for col = l*64+w*4+p*2, k = iq*32+lane
    unsigned long long u2[8][2];
#pragma unroll
    for (int iq = 0; iq < 8; ++iq)
#pragma unroll
        for (int p = 0; p < 2; ++p) {
            int k   = iq * 32 + lane;
            int col = l * 64 + w * 4 + p * 2;
            u2[iq][p] = *(const unsigned long long*)&g_Up[(size_t)k * G4 + col];
        }

    // butterfly-output source lanes for this lane's gate gather (bq = lane&3)
    int src[4];
#pragma unroll
    for (int cc = 0; cc < 4; ++cc) {
        int m = (lane & 3) * 4 + cc;
        src[cc] = (((m >> 3) & 1) << 4) | (((m >> 2) & 1) << 3) |
                  (((m >> 1) & 1) << 2) | ((m & 1) << 1);
    }

    float cstate = 0.f;
    float4 xnext = make_float4(0.f, 0.f, 0.f, 0.f);
    if (lane < 4)
        xnext = __ldg((const float4*)(g_xg + ((size_t)0 * NCTA + cta) * 256 + lane * 64 + w * 4));

    for (int t = 0; t < S; ++t) {
        float4 xcur = xnext;
        if (lane < 4 && t + 1 < S)
            xnext = __ldg((const float4*)(g_xg + ((size_t)(t + 1) * NCTA + cta) * 256 + lane * 64 + w * 4));

        // wait for h_{t-1}: poll one word per 16B quad (STG.128 atomicity => quad valid)
        const float* hb = g_hseq + (size_t)t * (B * H) + g * 1024;
        if (t > 0 && tid < 256) {
            const unsigned* wp = (const unsigned*)(hb + tid * 4);
            unsigned v;
            do {
                asm volatile("ld.volatile.global.b32 %0, [%1];" : "=r"(v) : "l"(wp));
            } while (v == SENT);
        }
        __syncthreads();

        // matvec: acc[p][bq], pairs over adjacent gate cols, h duplicated per batch
        unsigned long long acc[2][4];
#pragma unroll
        for (int p = 0; p < 2; ++p)
#pragma unroll
            for (int bq = 0; bq < 4; ++bq) acc[p][bq] = 0ull;

#pragma unroll
        for (int ih = 0; ih < 2; ++ih) {
            float4 hv[4];
#pragma unroll
            for (int j = 0; j < 4; ++j)
                hv[j] = *(const float4*)(hb + (size_t)((ih * 4 + j) * 32 + lane) * 4);
#pragma unroll
            for (int j = 0; j < 4; ++j) {
                int iq = ih * 4 + j;
                unsigned long long d0, d1, d2, d3;
                asm("mov.b64 %0, {%1, %1};" : "=l"(d0) : "f"(hv[j].x));
                asm("mov.b64 %0, {%1, %1};" : "=l"(d1) : "f"(hv[j].y));
                asm("mov.b64 %0, {%1, %1};" : "=l"(d2) : "f"(hv[j].z));
                asm("mov.b64 %0, {%1, %1};" : "=l"(d3) : "f"(hv[j].w));
#pragma unroll
                for (int p = 0; p < 2; ++p) {
                    asm("fma.rn.f32x2 %0, %1, %2, %0;" : "+l"(acc[p][0]) : "l"(u2[iq][p]), "l"(d0));
                    asm("fma.rn.f32x2 %0, %1, %2, %0;" : "+l"(acc[p][1]) : "l"(u2[iq][p]), "l"(d1));
                    asm("fma.rn.f32x2 %0, %1, %2, %0;" : "+l"(acc[p][2]) : "l"(u2[iq][p]), "l"(d2));
                    asm("fma.rn.f32x2 %0, %1, %2, %0;" : "+l"(acc[p][3]) : "l"(u2[iq][p]), "l"(d3));
                }
            }
        }

        // unpack: v[m], m = bq*4 + cc, cc = p*2 + half
        float v[16];
#pragma unroll
        for (int p = 0; p < 2; ++p)
#pragma unroll
            for (int bq = 0; bq < 4; ++bq) {
                unsigned long long a = acc[p][bq];
                v[bq * 4 + p * 2 + 0] = __uint_as_float((unsigned)a);
                v[bq * 4 + p * 2 + 1] = __uint_as_float((unsigned)(a >> 32));
            }

        // warp butterfly reduction over 32 lanes (k-slices), 16 outputs
        // final: even lane L holds m = (L>>4&1)*8 + (L>>3&1)*4 + (L>>2&1)*2 + (L>>1&1)
        {
            bool b4 = (lane & 16) != 0;
#pragma unroll
            for (int m = 0; m < 8; ++m) {
                float send = b4 ? v[m] : v[m + 8];
                float recv = __shfl_xor_sync(0xffffffffu, send, 16);
                v[m] = (b4 ? v[m + 8] : v[m]) + recv;
            }
            bool b3 = (lane & 8) != 0;
#pragma unroll
            for (int m = 0; m < 4; ++m) {
                float send = b3 ? v[m] : v[m + 4];
                float recv = __shfl_xor_sync(0xffffffffu, send, 8);
                v[m] = (b3 ? v[m + 4] : v[m]) + recv;
            }
            bool b2 = (lane & 4) != 0;
#pragma unroll
            for (int m = 0; m < 2; ++m) {
                float send = b2 ? v[m] : v[m + 2];
                float recv = __shfl_xor_sync(0xffffffffu, send, 4);
                v[m] = (b2 ? v[m + 2] : v[m]) + recv;
            }
            bool b1 = (lane & 2) != 0;
            {
                float send = b1 ? v[0] : v[1];
                float recv = __shfl_xor_sync(0xffffffffu, send, 2);
                v[0] = (b1 ? v[1] : v[0]) + recv;
            }
            v[0] += __shfl_xor_sync(0xffffffffu, v[0], 1);
        }

        // gather this lane's 4 gate sums (batch = lane&3); compute gates in lanes 0..3
        float s0 = __shfl_sync(0xffffffffu, v[0], src[0]);
        float s1 = __shfl_sync(0xffffffffu, v[0], src[1]);
        float s2 = __shfl_sync(0xffffffffu, v[0], src[2]);
        float s3 = __shfl_sync(0xffffffffu, v[0], src[3]);

        float hh = 0.f;
        if (lane < 4) {
            float zf = s0 + xcur.x;
            float zi = s1 + xcur.y;
            float zc = s2 + xcur.z;
            float zo = s3 + xcur.w;
            float f  = sig_(zf);
            float ii = sig_(zi);
            float gg = tanh_(zc);
            float oo = sig_(zo);
            cstate = fmaf(f, cstate, ii * gg);
            hh = oo * tanh_(cstate);
        }

        // publish h_t quad (dim l*16+w, batches 0..3) via one STG.128 from lane 0
        float h1 = __shfl_sync(0xffffffffu, hh, 1);
        float h2 = __shfl_sync(0xffffffffu, hh, 2);
        float h3 = __shfl_sync(0xffffffffu, hh, 3);
        if (lane == 0) {
            float4 q = make_float4(hh, h1, h2, h3);
            *(float4*)(g_hseq + (size_t)(t + 1) * (B * H) + g * 1024 + (size_t)(l * 16 + w) * 4) = q;
        }

        // off-critical-path output stores
        if (lane < 4) {
            int b   = g * 4 + lane;
            int dim = l * 16 + w;
            out[(size_t)b * (S * H) + (size_t)t * H + dim] = hh;
            if (t == S - 1) {
                size_t base = (size_t)B * S * H;
                if ((size_t)out_size >= base + 2 * (size_t)B * H) {
                    out[base + (size_t)b * H + dim] = hh;
                    out[base + (size_t)B * H + (size_t)b * H + dim] = cstate;
                }
            }
        }
    }
}

extern "C" void kernel_launch(void* const* d_in, const int* in_sizes, int n_in,
                              void* d_out, int out_size) {
    (void)in_sizes; (void)n_in;
    const float* x  = (const float*)d_in[0];
    const float* Wf = (const float*)d_in[1];
    const float* Uf = (const float*)d_in[2];
    const float* bf = (const float*)d_in[3];
    const float* Wi = (const float*)d_in[4];
    const float* Ui = (const float*)d_in[5];
    const float* bi = (const float*)d_in[6];
    const float* Wo = (const float*)d_in[7];
    const float* Uo = (const float*)d_in[8];
    const float* bo = (const float*)d_in[9];
    const float* Wc = (const float*)d_in[10];
    const float* Uc = (const float*)d_in[11];
    const float* bc = (const float*)d_in[12];

    pack_kernel<<<1024, 256>>>(Wf, Wi, Wc, Wo, Uf, Ui, Uc, Uo, bf, bi, bc, bo);
    hinit_kernel<<<4096, 256>>>();
    gemm_xg_kernel<<<dim3(G4 / BN, (S * B) / BM), 256>>>(x);
    lstm_kernel<<<NCTA, NTHR2>>>((float*)d_out, out_size);
}

// round 17
// speedup vs baseline: 1.0580x; 1.0580x over previous
#include <cuda_runtime.h>
#include <cstdint>

#define S 2048
#define B 32
#define I 256
#define H 256
#define G4 1024
#define NCTA 128
#define NTHR2 512
#define GD 16     // CTAs per group
#define SENT 0x7FC000AAu   // NaN sentinel (gates can never produce NaN)

// Static device scratch (no cudaMalloc allowed).
__device__ float g_Wp[I * G4];                 // packed input weights  [k][colp]
__device__ float g_Up[H * G4];                 // packed recurrent wts  [k][colp]
__device__ float g_bp[G4];                     // packed bias
__device__ float g_xg[(size_t)S * B * G4];     // input projections [t][cta][bq][64]
__device__ float g_hseq[(size_t)(S + 1) * B * H];  // h history [t][b][dim]; slot 0 = zeros

// colp mapping: gate = colp&3 (0=f,1=i,2=c,3=o), jl = (colp>>2)&15, l = colp>>6
// hidden dim j = l*16 + jl. CTA (g,l) owns batches 4g..4g+3 and cols l*64..l*64+63.
__global__ void pack_kernel(
    const float* __restrict__ Wf, const float* __restrict__ Wi,
    const float* __restrict__ Wc, const float* __restrict__ Wo,
    const float* __restrict__ Uf, const float* __restrict__ Ui,
    const float* __restrict__ Uc, const float* __restrict__ Uo,
    const float* __restrict__ bf, const float* __restrict__ bi,
    const float* __restrict__ bc, const float* __restrict__ bo)
{
    int idx = blockIdx.x * blockDim.x + threadIdx.x;
    if (idx < I * G4) {
        int k    = idx >> 10;
        int colp = idx & 1023;
        int g    = colp & 3;
        int jl   = (colp >> 2) & 15;
        int l    = colp >> 6;
        int j    = l * 16 + jl;
        const float* W = (g == 0) ? Wf : (g == 1) ? Wi : (g == 2) ? Wc : Wo;
        const float* U = (g == 0) ? Uf : (g == 1) ? Ui : (g == 2) ? Uc : Uo;
        g_Wp[idx] = W[k * H + j];
        g_Up[idx] = U[k * H + j];
        if (k == 0) {
            const float* bv = (g == 0) ? bf : (g == 1) ? bi : (g == 2) ? bc : bo;
            g_bp[colp] = bv[j];
        }
    }
}

// Prefill h history: slot 0 = zeros (h_{-1}), slots 1..S = sentinel NaN.
__global__ void hinit_kernel()
{
    size_t tot = (size_t)(S + 1) * B * H;
    size_t stride = (size_t)gridDim.x * blockDim.x;
    float sent = __uint_as_float(SENT);
    for (size_t i = (size_t)blockIdx.x * blockDim.x + threadIdx.x; i < tot; i += stride)
        g_hseq[i] = (i < (size_t)B * H) ? 0.f : sent;
}

// ---------------- Phase 1: xg = x @ Wp + bp (f32x2 packed), output [t][cta][bq][64] ----
#define BM 128
#define BN 128
#define BK 16

__global__ __launch_bounds__(256) void gemm_xg_kernel(const float* __restrict__ x)
{
    __shared__ float As[BK][BM + 4];   // transposed A tile
    __shared__ float Bs[BK][BN];

    int tid = threadIdx.x;
    int r0 = blockIdx.y * BM;   // rows r = t*B + b
    int c0 = blockIdx.x * BN;
    int tr = tid >> 4;          // 0..15 -> rows tr*8..+7
    int tc = tid & 15;          // 0..15 -> cols tc*8..+7 (4 pairs)

    int aRow = tid >> 1;              // 0..127
    int aK   = (tid & 1) * 8;         // 0 or 8
    int bK   = tid >> 4;              // 0..15
    int bC   = (tid & 15) << 3;       // 0..120

    int r  = r0 + aRow;
    int bb = r & 31;
    int tt = r >> 5;
    const float* aptr = x + ((size_t)bb * S + tt) * I + aK;

    // acc[r][p] = f32x2 pair for cols (tc*8 + 2p, tc*8 + 2p + 1)
    unsigned long long acc[8][4];
#pragma unroll
    for (int i2 = 0; i2 < 8; ++i2)
#pragma unroll
        for (int p = 0; p < 4; ++p) acc[i2][p] = 0ull;

    for (int k0 = 0; k0 < I; k0 += BK) {
        float4 a1 = *(const float4*)(aptr + k0);
        float4 a2 = *(const float4*)(aptr + k0 + 4);
        As[aK + 0][aRow] = a1.x;
        As[aK + 1][aRow] = a1.y;
        As[aK + 2][aRow] = a1.z;
        As[aK + 3][aRow] = a1.w;
        As[aK + 4][aRow] = a2.x;
        As[aK + 5][aRow] = a2.y;
        As[aK + 6][aRow] = a2.z;
        As[aK + 7][aRow] = a2.w;
        float4 bv1 = *(const float4*)(g_Wp + (size_t)(k0 + bK) * G4 + c0 + bC);
        float4 bv2 = *(const float4*)(g_Wp + (size_t)(k0 + bK) * G4 + c0 + bC + 4);
        *(float4*)&Bs[bK][bC]     = bv1;
        *(float4*)&Bs[bK][bC + 4] = bv2;
        __syncthreads();
#pragma unroll
        for (int kk = 0; kk < BK; ++kk) {
            // B pairs: 8 cols = 4 u64 (two LDS.128)
            ulonglong2 b01 = *(const ulonglong2*)&Bs[kk][tc << 3];
            ulonglong2 b23 = *(const ulonglong2*)&Bs[kk][(tc << 3) + 4];
            // A: 8 rows (two LDS.128, warp-broadcast)
            float4 a4lo = *(const float4*)&As[kk][tr << 3];
            float4 a4hi = *(const float4*)&As[kk][(tr << 3) + 4];
            float av[8] = {a4lo.x, a4lo.y, a4lo.z, a4lo.w, a4hi.x, a4hi.y, a4hi.z, a4hi.w};
#pragma unroll
            for (int i2 = 0; i2 < 8; ++i2) {
                unsigned long long ad;
                asm("mov.b64 %0, {%1, %1};" : "=l"(ad) : "f"(av[i2]));
                asm("fma.rn.f32x2 %0, %1, %2, %0;" : "+l"(acc[i2][0]) : "l"(ad), "l"(b01.x));
                asm("fma.rn.f32x2 %0, %1, %2, %0;" : "+l"(acc[i2][1]) : "l"(ad), "l"(b01.y));
                asm("fma.rn.f32x2 %0, %1, %2, %0;" : "+l"(acc[i2][2]) : "l"(ad), "l"(b23.x));
                asm("fma.rn.f32x2 %0, %1, %2, %0;" : "+l"(acc[i2][3]) : "l"(ad), "l"(b23.y));
            }
        }
        __syncthreads();
    }

    // write out: 8 cols per thread = 2 float4 blocks, each within a 64-col block
#pragma unroll
    for (int sub = 0; sub < 2; ++sub) {
        int col = c0 + (tc << 3) + sub * 4;   // 4-aligned
        int l   = col >> 6;
        int c63 = col & 63;
        float4 bias = *(const float4*)&g_bp[col];
        int p0 = sub * 2;
#pragma unroll
        for (int i2 = 0; i2 < 8; ++i2) {
            int rr  = r0 + (tr << 3) + i2;
            int tt2 = rr >> 5;
            int bb2 = rr & 31;
            int grp = bb2 >> 2;
            int bq  = bb2 & 3;
            unsigned long long q0 = acc[i2][p0];
            unsigned long long q1 = acc[i2][p0 + 1];
            float4 o;
            o.x = __uint_as_float((unsigned)q0) + bias.x;
            o.y = __uint_as_float((unsigned)(q0 >> 32)) + bias.y;
            o.z = __uint_as_float((unsigned)q1) + bias.z;
            o.w = __uint_as_float((unsigned)(q1 >> 32)) + bias.w;
            *(float4*)(g_xg + (((size_t)tt2 * NCTA + grp * GD + l) * 4 + bq) * 64 + c63) = o;
        }
    }
}

// ---------------- Phase 2: persistent recurrence (R13 verbatim — frozen) ----------------
__device__ __forceinline__ float sig_(float v) {
    return __fdividef(1.f, 1.f + __expf(-v));
}
__device__ __forceinline__ float tanh_(float v) {
    return 1.f - __fdividef(2.f, 1.f + __expf(2.f * v));
}

__global__ __launch_bounds__(NTHR2, 1) void lstm_kernel(float* __restrict__ out, int out_size)
{
    __shared__ float xs[64][4];       // staged xg [col64][bq]
    __shared__ float z_s[16][4][4];   // [dimw][gate][bq]

    int cta  = blockIdx.x;
    int g    = cta >> 4;              // batch group
    int l    = cta & 15;              // dim slice
    int tid  = threadIdx.x;
    int lane = tid & 31;
    int w    = tid >> 5;              // warp -> gate cols w*4..w*4+3

    // hoist U into registers (time-invariant)
    unsigned long long u2[2][2][4];
#pragma unroll
    for (int iq = 0; iq < 2; ++iq)
#pragma unroll
        for (int pp = 0; pp < 2; ++pp)
#pragma unroll
            for (int cc = 0; cc < 4; ++cc) {
                int col = l * 64 + w * 4 + cc;
                int k   = (iq * 32 + lane) * 4 + pp * 2;
                unsigned lo = __float_as_uint(g_Up[(size_t)k * G4 + col]);
                unsigned hi = __float_as_uint(g_Up[(size_t)(k + 1) * G4 + col]);
                u2[iq][pp][cc] = ((unsigned long long)hi << 32) | lo;
            }

    int dimw = tid >> 2;              // gate threads (tid<64)
    int bq_g = tid & 3;
    float cstate = 0.f;

    // xg prefetch threads (tid<64): bq = tid>>4, col offset = (tid&15)*4
    int pbq = tid >> 4;
    int pc  = (tid & 15) * 4;
    float4 xv = make_float4(0.f, 0.f, 0.f, 0.f);
    if (tid < 64)
        xv = __ldg((const float4*)(g_xg + (((size_t)0 * NCTA + cta) * 4 + pbq) * 64 + pc));

    // poller assignment (tid<256): batch quad bq = tid>>6, quad index q = tid&63
    int pl_bq = tid >> 6;
    int pl_q  = tid & 63;

    __syncthreads();

    for (int t = 0; t < S; ++t) {
        // park this step's xg; issue next step's prefetch (overlaps the wait)
        if (tid < 64) {
            xs[pc + 0][pbq] = xv.x;
            xs[pc + 1][pbq] = xv.y;
            xs[pc + 2][pbq] = xv.z;
            xs[pc + 3][pbq] = xv.w;
            if (t + 1 < S)
                xv = __ldg((const float4*)(g_xg + (((size_t)(t + 1) * NCTA + cta) * 4 + pbq) * 64 + pc));
        }

        // wait for h_{t-1}: poll the DATA itself (one word per 16B quad;
        // STG.128 atomicity makes the whole quad valid once any word != SENT)
        const float* hs = g_hseq + (size_t)t * (B * H) + (size_t)(g * 4) * H;
        if (t > 0 && tid < 256) {
            const unsigned* wp = (const unsigned*)(hs + pl_bq * H + pl_q * 4);
            unsigned v;
            do {
                asm volatile("ld.volatile.global.b32 %0, [%1];" : "=r"(v) : "l"(wp));
            } while (v == SENT);
        }
        __syncthreads();

        // load h_{t-1} (plain LDG: fresh lines, never stale in L1)
        float4 hq[2][4];
#pragma unroll
        for (int iq = 0; iq < 2; ++iq)
#pragma unroll
            for (int bq = 0; bq < 4; ++bq)
                hq[iq][bq] = *(const float4*)(hs + bq * H + (iq * 32 + lane) * 4);

        unsigned long long acc[4][4];   // [cc][bq]
#pragma unroll
        for (int cc = 0; cc < 4; ++cc)
#pragma unroll
            for (int bq = 0; bq < 4; ++bq) acc[cc][bq] = 0ull;

#pragma unroll
        for (int iq = 0; iq < 2; ++iq)
#pragma unroll
            for (int bq = 0; bq < 4; ++bq) {
                unsigned long long hx =
                    ((unsigned long long)__float_as_uint(hq[iq][bq].y) << 32) | __float_as_uint(hq[iq][bq].x);
                unsigned long long hy =
                    ((unsigned long long)__float_as_uint(hq[iq][bq].w) << 32) | __float_as_uint(hq[iq][bq].z);
#pragma unroll
                for (int cc = 0; cc < 4; ++cc) {
                    asm("fma.rn.f32x2 %0, %1, %2, %0;"
                        : "+l"(acc[cc][bq]) : "l"(u2[iq][0][cc]), "l"(hx));
                    asm("fma.rn.f32x2 %0, %1, %2, %0;"
                        : "+l"(acc[cc][bq]) : "l"(u2[iq][1][cc]), "l"(hy));
                }
            }

        // horizontal pair add -> v[m], m = cc*4+bq
        float v[16];
#pragma unroll
        for (int cc = 0; cc < 4; ++cc)
#pragma unroll
            for (int bq = 0; bq < 4; ++bq) {
                unsigned long long a = acc[cc][bq];
                v[cc * 4 + bq] =
                    __uint_as_float((unsigned)a) + __uint_as_float((unsigned)(a >> 32));
            }

        // warp butterfly reduction over 32 lanes (k-slices), 16 outputs
        {
            bool b4 = (lane & 16) != 0;
#pragma unroll
            for (int m = 0; m < 8; ++m) {
                float send = b4 ? v[m] : v[m + 8];
                float recv = __shfl_xor_sync(0xffffffffu, send, 16);
                v[m] = (b4 ? v[m + 8] : v[m]) + recv;
            }
            bool b3 = (lane & 8) != 0;
#pragma unroll
            for (int m = 0; m < 4; ++m) {
                float send = b3 ? v[m] : v[m + 4];
                float recv = __shfl_xor_sync(0xffffffffu, send, 8);
                v[m] = (b3 ? v[m + 4] : v[m]) + recv;
            }
            bool b2 = (lane & 4) != 0;
#pragma unroll
            for (int m = 0; m < 2; ++m) {
                float send = b2 ? v[m] : v[m + 2];
                float recv = __shfl_xor_sync(0xffffffffu, send, 4);
                v[m] = (b2 ? v[m + 2] : v[m]) + recv;
            }
            bool b1 = (lane & 2) != 0;
            {
                float send = b1 ? v[0] : v[1];
                float recv = __shfl_xor_sync(0xffffffffu, send, 2);
                v[0] = (b1 ? v[1] : v[0]) + recv;
            }
            v[0] += __shfl_xor_sync(0xffffffffu, v[0], 1);
        }
        if ((lane & 1) == 0) {
            int m = ((lane >> 4) & 1) * 8 + ((lane >> 3) & 1) * 4 +
                    ((lane >> 2) & 1) * 2 + ((lane >> 1) & 1);
            z_s[w][m >> 2][m & 3] = v[0];
        }
        __syncthreads();

        float hh = 0.f;
        if (tid < 64) {
            float zf = z_s[dimw][0][bq_g] + xs[dimw * 4 + 0][bq_g];
            float zi = z_s[dimw][1][bq_g] + xs[dimw * 4 + 1][bq_g];
            float zc = z_s[dimw][2][bq_g] + xs[dimw * 4 + 2][bq_g];
            float zo = z_s[dimw][3][bq_g] + xs[dimw * 4 + 3][bq_g];
            float f  = sig_(zf);
            float ii = sig_(zi);
            float gg = tanh_(zc);
            float oo = sig_(zo);
            cstate = fmaf(f, cstate, ii * gg);
            hh = oo * tanh_(cstate);

            // publish h_t via STG.128 quads: gather 4 dims of same batch via warp shuffles.
            float v0 = hh;
            float v1 = __shfl_down_sync(0xffffffffu, hh, 4);
            float v2 = __shfl_down_sync(0xffffffffu, hh, 8);
            float v3 = __shfl_down_sync(0xffffffffu, hh, 12);
            if ((lane & 12) == 0) {
                int q    = lane >> 4;                // 0 or 1 within warp
                int dim0 = (tid >> 5) * 8 + q * 4;   // warp*8 + q*4
                int b    = lane & 3;
                float4 outq = make_float4(v0, v1, v2, v3);
                *(float4*)(g_hseq + (size_t)(t + 1) * (B * H) +
                           (size_t)(g * 4 + b) * H + l * 16 + dim0) = outq;
            }
        }

        // off-critical-path output stores
        if (tid < 64) {
            int b   = g * 4 + bq_g;
            int dim = l * 16 + dimw;
            out[(size_t)b * (S * H) + (size_t)t * H + dim] = hh;
            if (t == S - 1) {
                size_t base = (size_t)B * S * H;
                if ((size_t)out_size >= base + 2 * (size_t)B * H) {
                    out[base + (size_t)b * H + dim] = hh;
                    out[base + (size_t)B * H + (size_t)b * H + dim] = cstate;
                }
            }
        }
        __syncthreads();
    }
}

extern "C" void kernel_launch(void* const* d_in, const int* in_sizes, int n_in,
                              void* d_out, int out_size) {
    (void)in_sizes; (void)n_in;
    const float* x  = (const float*)d_in[0];
    const float* Wf = (const float*)d_in[1];
    const float* Uf = (const float*)d_in[2];
    const float* bf = (const float*)d_in[3];
    const float* Wi = (const float*)d_in[4];
    const float* Ui = (const float*)d_in[5];
    const float* bi = (const float*)d_in[6];
    const float* Wo = (const float*)d_in[7];
    const float* Uo = (const float*)d_in[8];
    const float* bo = (const float*)d_in[9];
    const float* Wc = (const float*)d_in[10];
    const float* Uc = (const float*)d_in[11];
    const float* bc = (const float*)d_in[12];

    pack_kernel<<<1024, 256>>>(Wf, Wi, Wc, Wo, Uf, Ui, Uc, Uo, bf, bi, bc, bo);
    hinit_kernel<<<4096, 256>>>();
    gemm_xg_kernel<<<dim3(G4 / BN, (S * B) / BM), 256>>>(x);
    lstm_kernel<<<NCTA, NTHR2>>>((float*)d_out, out_size);
}